// round 16
// baseline (speedup 1.0000x reference)
#include <cuda_runtime.h>
#include <cuda_fp16.h>

// RAE GRU enc-dec.
// K0: pad/transpose Wih (+ lin transpose). K0b: fold M=dWih*linW, c=dWih*linb+dbih.
// K1: precompute all encoder gi (fp16). K2: encoder (1 team-bar/step).
// K3: decoder with gi FOLDED into the h-GEMM for r,z gates (M added to dWhh),
//     gi_n + lin streamed coalesced from L2 -> ONE team-barrier per step,
//     no oS exchange. t=0 special-cased (o0=0).

typedef unsigned long long u64;

__device__ __forceinline__ u64 pk2(float lo, float hi) {
    u64 r; asm("mov.b64 %0, {%1,%2};" : "=l"(r) : "f"(lo), "f"(hi)); return r;
}
__device__ __forceinline__ float red2(u64 v) {
    float lo, hi; asm("mov.b64 {%0,%1}, %2;" : "=f"(lo), "=f"(hi) : "l"(v));
    return lo + hi;
}
__device__ __forceinline__ void fma2(u64& d, u64 a, u64 b) {
    asm("fma.rn.f32x2 %0, %1, %2, %0;" : "+l"(d) : "l"(a), "l"(b));
}
__device__ __forceinline__ float tanh_mufu(float v) {
    float r; asm("tanh.approx.f32 %0, %1;" : "=f"(r) : "f"(v)); return r;
}
__device__ __forceinline__ float sigm(float v) {
    return fmaf(tanh_mufu(0.5f * v), 0.5f, 0.5f);
}
__device__ __forceinline__ void team_bar(int id) {
    asm volatile("bar.sync %0, 128;" :: "r"(id) : "memory");
}

constexpr int X  = 38;
constexpr int XP = 40;
constexpr int H  = 128;
constexpr int G  = 384;
constexpr int T  = 128;
constexpr int B  = 2048;
constexpr int BT = 16;
constexpr int NB = B / BT;  // 128 CTAs
constexpr int NT = 256;
constexpr int RR = 8;       // batch rows per thread

__device__ float  g_wih_t[(XP / 4) * G * 4];
__device__ float  g_henc[B * H];
__device__ __half g_gi[B * T * G];
__device__ float  g_M[G * H];                 // M = dWih * linW
__device__ float  g_c[G];                     // c = dWih*linb + dbih
__device__ float  g_mn_t[(H / 4) * H * 4];    // M n-rows, [kb][col][kk] coalesced
__device__ float  g_lin_t[(H / 4) * X * 4];   // linW,     [kb][col][kk] coalesced

// ------------------- K0: pad/transpose enc Wih + lin transpose -------------
__global__ void pad_wih_kernel(const float* __restrict__ ewih,
                               const float* __restrict__ linW) {
    int i = blockIdx.x * blockDim.x + threadIdx.x;
    if (i < G * XP) {
        int col = i / XP, k = i - col * XP;
        int dst = (k >> 2) * (G * 4) + col * 4 + (k & 3);
        g_wih_t[dst] = (k < X) ? ewih[col * X + k] : 0.f;
    }
    if (i < X * H) {
        int col = i / H, k = i - col * H;
        g_lin_t[(k >> 2) * (X * 4) + col * 4 + (k & 3)] = linW[i];
    }
}

// ------------------- K0b: fold M = dWih*linW, c = dWih*linb + dbih ---------
__global__ void fold_kernel(const float* __restrict__ dWih,
                            const float* __restrict__ linW,
                            const float* __restrict__ linb,
                            const float* __restrict__ dbih) {
    int i = blockIdx.x * blockDim.x + threadIdx.x;
    if (i < G * H) {
        int col = i >> 7, k = i & 127;
        float s = 0.f;
        #pragma unroll 2
        for (int j = 0; j < X; ++j) s += dWih[col * X + j] * linW[j * H + k];
        g_M[i] = s;
        if (col >= 256)   // n-rows, transposed coalesced layout for streaming
            g_mn_t[(k >> 2) * (H * 4) + (col - 256) * 4 + (k & 3)] = s;
    }
    if (i < G) {
        float s = dbih[i];
        for (int j = 0; j < X; ++j) s += dWih[i * X + j] * linb[j];
        g_c[i] = s;
    }
}

// ------------------- K1: encoder gi precompute GEMM ------------------------
constexpr int K1R = 32;
__global__ void __launch_bounds__(512, 1)
gi_kernel(const float* __restrict__ x, const float* __restrict__ ebih) {
    __shared__ float xs[K1R * XP];
    const int tid = threadIdx.x;
    const int gr0 = blockIdx.x * K1R;

    for (int i = tid; i < K1R * XP; i += 512) {
        int rr = i / XP, k = i - rr * XP;
        xs[i] = (k < X) ? x[(gr0 + rr) * X + k] : 0.f;
    }
    __syncthreads();

    const int rg = tid >> 7;
    const int ct = tid & 127;
    const int r0 = rg << 3;

    u64 acc[8][3];
    #pragma unroll
    for (int i = 0; i < 3; ++i) {
        float bi = ebih[ct + (i << 7)];
        #pragma unroll
        for (int r = 0; r < 8; ++r) acc[r][i] = pk2(bi, 0.f);
    }
    #pragma unroll
    for (int kb = 0; kb < XP / 4; ++kb) {
        int k = kb << 2;
        ulonglong2 xv[8];
        #pragma unroll
        for (int r = 0; r < 8; ++r)
            xv[r] = *(const ulonglong2*)(xs + (r0 + r) * XP + k);
        #pragma unroll
        for (int i = 0; i < 3; ++i) {
            ulonglong2 wv = *(const ulonglong2*)(g_wih_t + kb * (G * 4) + (ct + (i << 7)) * 4);
            #pragma unroll
            for (int r = 0; r < 8; ++r) {
                fma2(acc[r][i], xv[r].x, wv.x);
                fma2(acc[r][i], xv[r].y, wv.y);
            }
        }
    }
    #pragma unroll
    for (int r = 0; r < 8; ++r) {
        int gr = gr0 + r0 + r;
        int b = gr >> 7, t = gr & (T - 1);
        int blk = b >> 4, lb = b & 15;
        int base = ((blk * T + t) * BT + lb) * G;
        #pragma unroll
        for (int i = 0; i < 3; ++i)
            g_gi[base + ct + (i << 7)] = __float2half(red2(acc[r][i]));
    }
}

// ------------------------- K2: encoder recurrence --------------------------
constexpr int ENC_SMB = (G * H + 2 * BT * H) * 4;   // 212992 B

__global__ void __launch_bounds__(NT, 1)
enc_kernel(const float* __restrict__ eWhh, const float* __restrict__ ebhh) {
    extern __shared__ float sm[];
    float* Ws = sm;
    float* hA = Ws + G * H;
    float* hB = hA + BT * H;

    const int tid = threadIdx.x;
    const int tm  = tid >> 7;
    const int ct  = tid & 127;
    const int r0  = tm << 3;
    const int swz = (ct & 31) << 2;
    const int blk = blockIdx.x;
    const int bid = tm + 1;

    for (int i = tid; i < G * H; i += NT) {
        int c = i >> 7, k = i & 127;
        Ws[(c << 7) + (k ^ ((c & 31) << 2))] = eWhh[i];
    }
    for (int i = tid; i < BT * H; i += NT) hA[i] = 0.f;
    float bh[3];
    #pragma unroll
    for (int i = 0; i < 3; ++i) bh[i] = ebhh[ct + (i << 7)];
    __syncthreads();

    float* hR = hA;
    float* hW = hB;
    float h_own[RR];
    #pragma unroll
    for (int r = 0; r < RR; ++r) h_own[r] = 0.f;

    for (int t = 0; t < T; ++t) {
        __half gv[RR][3];
        int gbase = (blk * T + t) * BT * G;
        #pragma unroll
        for (int r = 0; r < RR; ++r)
            #pragma unroll
            for (int i = 0; i < 3; ++i)
                gv[r][i] = g_gi[gbase + (r0 + r) * G + ct + (i << 7)];

        u64 aH[RR][3];
        #pragma unroll
        for (int r = 0; r < RR; ++r)
            #pragma unroll
            for (int i = 0; i < 3; ++i) aH[r][i] = pk2(bh[i], 0.f);

        #pragma unroll 8
        for (int kb = 0; kb < H / 4; ++kb) {
            int k = kb << 2;
            ulonglong2 hv[RR];
            #pragma unroll
            for (int r = 0; r < RR; ++r)
                hv[r] = *(const ulonglong2*)(hR + (r0 + r) * H + k);
            #pragma unroll
            for (int i = 0; i < 3; ++i) {
                ulonglong2 wv = *(const ulonglong2*)(Ws + ((ct + (i << 7)) << 7) + (k ^ swz));
                #pragma unroll
                for (int r = 0; r < RR; ++r) {
                    fma2(aH[r][i], hv[r].x, wv.x);
                    fma2(aH[r][i], hv[r].y, wv.y);
                }
            }
        }

        #pragma unroll
        for (int r = 0; r < RR; ++r) {
            float rr = sigm(__half2float(gv[r][0]) + red2(aH[r][0]));
            float zz = sigm(__half2float(gv[r][1]) + red2(aH[r][1]));
            float nn = tanh_mufu(__half2float(gv[r][2]) + rr * red2(aH[r][2]));
            float hn = (1.f - zz) * nn + zz * h_own[r];
            h_own[r] = hn;
            hW[(r0 + r) * H + ct] = hn;
        }
        team_bar(bid);
        float* tmp = hR; hR = hW; hW = tmp;
    }
    __syncthreads();
    for (int i = tid; i < BT * H; i += NT) g_henc[blk * BT * H + i] = hR[i];
}

// ------------------------- K3: decoder recurrence (folded gi) --------------
// smem: Ws[384*128] (cols 0..255: dWhh+M combined r,z; 256..383: dWhh n)
//       + hA[16*128] + hB[16*128]  = 212992 B
constexpr int DEC_SMB = (G * H + 2 * BT * H) * 4;

__global__ void __launch_bounds__(NT, 1)
dec_kernel(const float* __restrict__ dWhh,
           const float* __restrict__ dbih, const float* __restrict__ dbhh,
           const float* __restrict__ linb,
           float* __restrict__ out) {
    extern __shared__ float sm[];
    float* Ws = sm;
    float* hA = Ws + G * H;
    float* hB = hA + BT * H;

    const int tid = threadIdx.x;
    const int tm  = tid >> 7;
    const int ctl = tid & 127;
    const int ct  = tm ? (127 - ctl) : ctl;   // team-1 reversal: SMSP balance
    const int r0  = tm << 3;
    const int swz = (ct & 31) << 2;
    const int blk = blockIdx.x;
    const int bid = tm + 1;
    const bool oc = (ct < X);

    for (int i = tid; i < G * H; i += NT) {
        int c = i >> 7, k = i & 127;
        float v = dWhh[i];
        if (c < 256) v += g_M[i];             // fold gi into r,z gates
        Ws[(c << 7) + (k ^ ((c & 31) << 2))] = v;
    }
    for (int i = tid; i < BT * H; i += NT) hA[i] = g_henc[blk * BT * H + i];
    // biases: main loop uses combined c+dbhh for r,z; c_n separate
    float brz[2], bn, cn;
    brz[0] = dbhh[ct] + g_c[ct];
    brz[1] = dbhh[ct + 128] + g_c[ct + 128];
    bn = dbhh[ct + 256];
    cn = g_c[ct + 256];
    const float lb = oc ? linb[ct] : 0.f;
    __syncthreads();

    float* hR = hA;
    float* hW = hB;
    float h_own[RR];
    #pragma unroll
    for (int r = 0; r < RR; ++r) h_own[r] = hR[(r0 + r) * H + ct];

    // ---- step 0 (special: o0 = 0 -> gi = dbih; gh r,z from PLAIN dWhh) ----
    {
        u64 a0[RR][3];
        #pragma unroll
        for (int r = 0; r < RR; ++r) {
            a0[r][0] = pk2(dbhh[ct], 0.f);
            a0[r][1] = pk2(dbhh[ct + 128], 0.f);
            a0[r][2] = pk2(bn, 0.f);
        }
        #pragma unroll 4
        for (int kb = 0; kb < H / 4; ++kb) {
            int k = kb << 2;
            ulonglong2 hv[RR];
            #pragma unroll
            for (int r = 0; r < RR; ++r)
                hv[r] = *(const ulonglong2*)(hR + (r0 + r) * H + k);
            ulonglong2 wr = *(const ulonglong2*)(dWhh + ct * H + k);           // plain
            ulonglong2 wz = *(const ulonglong2*)(dWhh + (ct + 128) * H + k);   // plain
            ulonglong2 wn = *(const ulonglong2*)(Ws + ((ct + 256) << 7) + (k ^ swz));
            #pragma unroll
            for (int r = 0; r < RR; ++r) {
                fma2(a0[r][0], hv[r].x, wr.x); fma2(a0[r][0], hv[r].y, wr.y);
                fma2(a0[r][1], hv[r].x, wz.x); fma2(a0[r][1], hv[r].y, wz.y);
                fma2(a0[r][2], hv[r].x, wn.x); fma2(a0[r][2], hv[r].y, wn.y);
            }
        }
        float bir = dbih[ct], biz = dbih[ct + 128], bin = dbih[ct + 256];
        #pragma unroll
        for (int r = 0; r < RR; ++r) {
            float rr = sigm(bir + red2(a0[r][0]));
            float zz = sigm(biz + red2(a0[r][1]));
            float nn = tanh_mufu(bin + rr * red2(a0[r][2]));
            float hn = (1.f - zz) * nn + zz * h_own[r];
            h_own[r] = hn;
            hW[(r0 + r) * H + ct] = hn;
        }
        team_bar(bid);
        float* tmp = hR; hR = hW; hW = tmp;
    }

    // ---- main loop s=1..T: one GEMM = combined gates + gi_n + lin out -----
    for (int s = 1; s <= T; ++s) {
        u64 aRZ[RR][2], aN[RR], aG[RR], aL[RR];
        #pragma unroll
        for (int r = 0; r < RR; ++r) {
            aRZ[r][0] = pk2(brz[0], 0.f);
            aRZ[r][1] = pk2(brz[1], 0.f);
            aN[r] = pk2(bn, 0.f);
            aG[r] = pk2(cn, 0.f);
            aL[r] = pk2(lb, 0.f);
        }
        #pragma unroll 4
        for (int kb = 0; kb < H / 4; ++kb) {
            int k = kb << 2;
            ulonglong2 hv[RR];
            #pragma unroll
            for (int r = 0; r < RR; ++r)
                hv[r] = *(const ulonglong2*)(hR + (r0 + r) * H + k);
            #pragma unroll
            for (int i = 0; i < 2; ++i) {
                ulonglong2 wv = *(const ulonglong2*)(Ws + ((ct + (i << 7)) << 7) + (k ^ swz));
                #pragma unroll
                for (int r = 0; r < RR; ++r) {
                    fma2(aRZ[r][i], hv[r].x, wv.x);
                    fma2(aRZ[r][i], hv[r].y, wv.y);
                }
            }
            {
                ulonglong2 wn = *(const ulonglong2*)(Ws + ((ct + 256) << 7) + (k ^ swz));
                ulonglong2 wg = *(const ulonglong2*)(g_mn_t + kb * (H * 4) + ct * 4);
                #pragma unroll
                for (int r = 0; r < RR; ++r) {
                    fma2(aN[r], hv[r].x, wn.x); fma2(aN[r], hv[r].y, wn.y);
                    fma2(aG[r], hv[r].x, wg.x); fma2(aG[r], hv[r].y, wg.y);
                }
            }
            if (oc) {
                ulonglong2 wl = *(const ulonglong2*)(g_lin_t + kb * (X * 4) + ct * 4);
                #pragma unroll
                for (int r = 0; r < RR; ++r) {
                    fma2(aL[r], hv[r].x, wl.x);
                    fma2(aL[r], hv[r].y, wl.y);
                }
            }
        }
        if (oc) {   // out[s-1] = lin(h_s)
            #pragma unroll
            for (int r = 0; r < RR; ++r)
                out[((blk * BT + r0 + r) * T + (s - 1)) * X + ct] = red2(aL[r]);
        }
        if (s == T) break;

        #pragma unroll
        for (int r = 0; r < RR; ++r) {
            float rr = sigm(red2(aRZ[r][0]));
            float zz = sigm(red2(aRZ[r][1]));
            float nn = tanh_mufu(red2(aG[r]) + rr * red2(aN[r]));
            float hn = (1.f - zz) * nn + zz * h_own[r];
            h_own[r] = hn;
            hW[(r0 + r) * H + ct] = hn;
        }
        team_bar(bid);
        float* tmp = hR; hR = hW; hW = tmp;
    }
}

extern "C" void kernel_launch(void* const* d_in, const int* in_sizes, int n_in,
                              void* d_out, int out_size) {
    const float* x    = (const float*)d_in[0];
    const float* eWih = (const float*)d_in[1];
    const float* eWhh = (const float*)d_in[2];
    const float* ebih = (const float*)d_in[3];
    const float* ebhh = (const float*)d_in[4];
    const float* dWih = (const float*)d_in[5];
    const float* dWhh = (const float*)d_in[6];
    const float* dbih = (const float*)d_in[7];
    const float* dbhh = (const float*)d_in[8];
    const float* linW = (const float*)d_in[9];
    const float* linb = (const float*)d_in[10];
    float* out = (float*)d_out;

    pad_wih_kernel<<<(G * XP + 255) / 256, 256>>>(eWih, linW);
    fold_kernel<<<(G * H + 255) / 256, 256>>>(dWih, linW, linb, dbih);
    gi_kernel<<<(B * T) / K1R, 512>>>(x, ebih);

    cudaFuncSetAttribute(enc_kernel, cudaFuncAttributeMaxDynamicSharedMemorySize, ENC_SMB);
    enc_kernel<<<NB, NT, ENC_SMB>>>(eWhh, ebhh);

    cudaFuncSetAttribute(dec_kernel, cudaFuncAttributeMaxDynamicSharedMemorySize, DEC_SMB);
    dec_kernel<<<NB, NT, DEC_SMB>>>(dWhh, dbih, dbhh, linb, out);
}